// round 3
// baseline (speedup 1.0000x reference)
#include <cuda_runtime.h>
#include <cuda_bf16.h>

#define D      1024
#define D4     (D / 4)          // 256 float4 per row
#define K      8
#define WARPS  8
#define THREADS (WARPS * 32)
#define ROWS_PER_WARP 8
#define ROWS_PER_BLOCK (WARPS * ROWS_PER_WARP)   // 64

__global__ __launch_bounds__(THREADS, 1)
void cmoe_router_kernel(const float* __restrict__ x,
                        const float* __restrict__ cent,
                        float* __restrict__ out_w,   // (N, K)
                        float* __restrict__ out_a,   // (N,) assignments as float
                        int nrows)
{
    __shared__ float4 sc[K * D4];     // 32 KB centroids
    __shared__ float  scn[K];         // centroid squared norms (fp32, correctly rounded)

    const int tid  = threadIdx.x;
    const int wid  = tid >> 5;
    const int lane = tid & 31;

    // Stage centroids into shared (vectorized)
    const float4* c4 = reinterpret_cast<const float4*>(cent);
    for (int i = tid; i < K * D4; i += THREADS) sc[i] = c4[i];
    __syncthreads();

    // Centroid norms: warp k reduces centroid k, in double (correctly rounded fp32 result)
    if (wid < K) {
        double s = 0.0;
        for (int j = lane; j < D4; j += 32) {
            float4 v = sc[wid * D4 + j];
            s += (double)v.x * v.x + (double)v.y * v.y
               + (double)v.z * v.z + (double)v.w * v.w;
        }
        #pragma unroll
        for (int o = 16; o; o >>= 1) s += __shfl_xor_sync(0xffffffffu, s, o);
        if (lane == 0) scn[wid] = (float)s;
    }
    __syncthreads();

    const int row0 = blockIdx.x * ROWS_PER_BLOCK + wid * ROWS_PER_WARP;
    if (row0 >= nrows) return;

    float acc[ROWS_PER_WARP][K];
    float xn[ROWS_PER_WARP];
    #pragma unroll
    for (int r = 0; r < ROWS_PER_WARP; ++r) {
        xn[r] = 0.f;
        #pragma unroll
        for (int k = 0; k < K; ++k) acc[r][k] = 0.f;
    }

    const float4* x4 = reinterpret_cast<const float4*>(x);

    // Main loop: 8 rows in flight, centroid float4 reused 8x per shared load
    #pragma unroll
    for (int it = 0; it < D4 / 32; ++it) {
        const int j = it * 32 + lane;
        float4 xv[ROWS_PER_WARP];
        #pragma unroll
        for (int r = 0; r < ROWS_PER_WARP; ++r) {
            xv[r] = x4[(size_t)(row0 + r) * D4 + j];
            xn[r] += xv[r].x * xv[r].x + xv[r].y * xv[r].y
                   + xv[r].z * xv[r].z + xv[r].w * xv[r].w;
        }
        #pragma unroll
        for (int k = 0; k < K; ++k) {
            const float4 cv = sc[k * D4 + j];
            #pragma unroll
            for (int r = 0; r < ROWS_PER_WARP; ++r) {
                acc[r][k] += xv[r].x * cv.x + xv[r].y * cv.y
                           + xv[r].z * cv.z + xv[r].w * cv.w;
            }
        }
    }

    // Cross-lane reduction in DOUBLE (epilogue only): our xn/acc inputs to the
    // final fp32 combine become correctly-rounded; remaining deviation vs the
    // reference equals only the reference's own accumulation noise.
    #pragma unroll
    for (int r = 0; r < ROWS_PER_WARP; ++r) {
        double xd = (double)xn[r];
        double ad[K];
        #pragma unroll
        for (int k = 0; k < K; ++k) ad[k] = (double)acc[r][k];
        #pragma unroll
        for (int o = 16; o; o >>= 1) {
            xd += __shfl_xor_sync(0xffffffffu, xd, o);
            #pragma unroll
            for (int k = 0; k < K; ++k)
                ad[k] += __shfl_xor_sync(0xffffffffu, ad[k], o);
        }
        xn[r] = (float)xd;
        #pragma unroll
        for (int k = 0; k < K; ++k) acc[r][k] = (float)ad[k];
    }

    // Lane r finishes row r: distances, argmin over fp32 d (matches reference:
    // jnp.argmin(dists) — sqrt-collapsed ties resolve to FIRST index via strict <),
    // softmax(-d) with max-subtraction.
    if (lane < ROWS_PER_WARP) {
        const int r   = lane;
        const int row = row0 + r;
        float d[K];
        float dmin = 3.402823466e38f;
        int   kmin = 0;
        #pragma unroll
        for (int k = 0; k < K; ++k) {
            // Reference rounding order: (||x||^2 + ||c||^2) - 2*(x.c),
            // separate roundings, no FMA contraction.
            float t1 = __fadd_rn(xn[r], scn[k]);
            float t2 = __fmul_rn(2.0f, acc[r][k]);   // exact (x2)
            float sq = __fsub_rn(t1, t2);
            d[k] = sqrtf(fmaxf(sq, 0.f));
            if (d[k] < dmin) { dmin = d[k]; kmin = k; }  // strict <: first min, on d not sq
        }
        float e[K];
        float sum = 0.f;
        #pragma unroll
        for (int k = 0; k < K; ++k) {
            e[k] = __expf(dmin - d[k]);
            sum += e[k];
        }
        const float inv = 1.f / sum;
        #pragma unroll
        for (int k = 0; k < K; ++k)
            out_w[(size_t)row * K + k] = e[k] * inv;
        out_a[row] = (float)kmin;
    }
}

extern "C" void kernel_launch(void* const* d_in, const int* in_sizes, int n_in,
                              void* d_out, int out_size)
{
    const float* x    = (const float*)d_in[0];
    const float* cent = (const float*)d_in[1];

    const int nrows = in_sizes[0] / D;              // 65536
    float* out_w = (float*)d_out;                   // (N, K) weights
    float* out_a = out_w + (size_t)nrows * K;       // (N,) assignments (as float)

    const int grid = (nrows + ROWS_PER_BLOCK - 1) / ROWS_PER_BLOCK;
    cmoe_router_kernel<<<grid, THREADS>>>(x, cent, out_w, out_a, nrows);
}

// round 5
// speedup vs baseline: 1.0834x; 1.0834x over previous
#include <cuda_runtime.h>
#include <cuda_bf16.h>

#define D      1024
#define D4     (D / 4)          // 256 float4 per row
#define K      8
#define WARPS  8
#define THREADS (WARPS * 32)
#define ROWS_PER_WARP 8
#define ROWS_PER_BLOCK (WARPS * ROWS_PER_WARP)   // 64

__global__ __launch_bounds__(THREADS, 2)        // force 2 blocks/SM (<=128 regs)
void cmoe_router_kernel(const float* __restrict__ x,
                        const float* __restrict__ cent,
                        float* __restrict__ out_w,   // (N, K)
                        float* __restrict__ out_a,   // (N,) assignments as float
                        int nrows)
{
    __shared__ float4 sc[K * D4];     // 32 KB centroids
    __shared__ float  scn[K];         // centroid squared norms (fp32, correctly rounded)

    const int tid  = threadIdx.x;
    const int wid  = tid >> 5;
    const int lane = tid & 31;

    // Stage centroids into shared (vectorized)
    const float4* c4 = reinterpret_cast<const float4*>(cent);
    for (int i = tid; i < K * D4; i += THREADS) sc[i] = c4[i];
    __syncthreads();

    // Centroid norms: warp k reduces centroid k, in double (correctly rounded fp32)
    if (wid < K) {
        double s = 0.0;
        for (int j = lane; j < D4; j += 32) {
            float4 v = sc[wid * D4 + j];
            s += (double)v.x * v.x + (double)v.y * v.y
               + (double)v.z * v.z + (double)v.w * v.w;
        }
        #pragma unroll
        for (int o = 16; o; o >>= 1) s += __shfl_xor_sync(0xffffffffu, s, o);
        if (lane == 0) scn[wid] = (float)s;
    }
    __syncthreads();

    const int row0 = blockIdx.x * ROWS_PER_BLOCK + wid * ROWS_PER_WARP;
    if (row0 >= nrows) return;

    float acc[ROWS_PER_WARP][K];
    float xn[ROWS_PER_WARP];
    #pragma unroll
    for (int r = 0; r < ROWS_PER_WARP; ++r) {
        xn[r] = 0.f;
        #pragma unroll
        for (int k = 0; k < K; ++k) acc[r][k] = 0.f;
    }

    // Single per-lane base pointer; all row/iter offsets become immediates.
    const float4* __restrict__ xb =
        reinterpret_cast<const float4*>(x) + (size_t)row0 * D4 + lane;
    const float4* __restrict__ scb = sc + lane;

    // Main loop: 8 rows in flight, centroid float4 reused 8x per shared load.
    // x is streamed once -> evict-first loads (__ldcs) to avoid L2 churn.
    #pragma unroll
    for (int it = 0; it < D4 / 32; ++it) {
        float4 xv[ROWS_PER_WARP];
        #pragma unroll
        for (int r = 0; r < ROWS_PER_WARP; ++r) {
            xv[r] = __ldcs(xb + it * 32 + r * D4);     // [base + imm], streaming
            xn[r] += xv[r].x * xv[r].x + xv[r].y * xv[r].y
                   + xv[r].z * xv[r].z + xv[r].w * xv[r].w;
        }
        #pragma unroll
        for (int k = 0; k < K; ++k) {
            const float4 cv = scb[it * 32 + k * D4];   // [smem base + imm]
            #pragma unroll
            for (int r = 0; r < ROWS_PER_WARP; ++r) {
                acc[r][k] += xv[r].x * cv.x + xv[r].y * cv.y
                           + xv[r].z * cv.z + xv[r].w * cv.w;
            }
        }
    }

    // Cross-lane reduction in DOUBLE (epilogue only): inputs to the final fp32
    // combine are correctly rounded (identical to the R3-passing version).
    #pragma unroll
    for (int r = 0; r < ROWS_PER_WARP; ++r) {
        double xd = (double)xn[r];
        double ad[K];
        #pragma unroll
        for (int k = 0; k < K; ++k) ad[k] = (double)acc[r][k];
        #pragma unroll
        for (int o = 16; o; o >>= 1) {
            xd += __shfl_xor_sync(0xffffffffu, xd, o);
            #pragma unroll
            for (int k = 0; k < K; ++k)
                ad[k] += __shfl_xor_sync(0xffffffffu, ad[k], o);
        }
        xn[r] = (float)xd;
        #pragma unroll
        for (int k = 0; k < K; ++k) acc[r][k] = (float)ad[k];
    }

    // Lane r finishes row r: distances, argmin over fp32 d (first-min ties),
    // softmax(-d) with max-subtraction. Identical numerics to R3.
    if (lane < ROWS_PER_WARP) {
        const int r   = lane;
        const int row = row0 + r;
        float d[K];
        float dmin = 3.402823466e38f;
        int   kmin = 0;
        #pragma unroll
        for (int k = 0; k < K; ++k) {
            float t1 = __fadd_rn(xn[r], scn[k]);
            float t2 = __fmul_rn(2.0f, acc[r][k]);   // exact (x2)
            float sq = __fsub_rn(t1, t2);
            d[k] = sqrtf(fmaxf(sq, 0.f));
            if (d[k] < dmin) { dmin = d[k]; kmin = k; }
        }
        float e[K];
        float sum = 0.f;
        #pragma unroll
        for (int k = 0; k < K; ++k) {
            e[k] = __expf(dmin - d[k]);
            sum += e[k];
        }
        const float inv = 1.f / sum;
        #pragma unroll
        for (int k = 0; k < K; ++k)
            out_w[(size_t)row * K + k] = e[k] * inv;
        out_a[row] = (float)kmin;
    }
}

extern "C" void kernel_launch(void* const* d_in, const int* in_sizes, int n_in,
                              void* d_out, int out_size)
{
    const float* x    = (const float*)d_in[0];
    const float* cent = (const float*)d_in[1];

    const int nrows = in_sizes[0] / D;              // 65536
    float* out_w = (float*)d_out;                   // (N, K) weights
    float* out_a = out_w + (size_t)nrows * K;       // (N,) assignments (as float)

    const int grid = (nrows + ROWS_PER_BLOCK - 1) / ROWS_PER_BLOCK;
    cmoe_router_kernel<<<grid, THREADS>>>(x, cent, out_w, out_a, nrows);
}